// round 1
// baseline (speedup 1.0000x reference)
#include <cuda_runtime.h>
#include <math.h>

#define N_NODES 50000
#define N_EDGES 800000
#define FEATS   128

// ---------------- scratch (static __device__, no allocation) ----------------
__device__ float g_wsum[N_NODES];
__device__ int   g_deg[N_NODES];
__device__ int   g_cursor[N_NODES];
__device__ int   g_off[N_NODES];
__device__ int   g_esrc[N_EDGES];
__device__ float g_ecoef[N_EDGES];
__device__ float g_aggF[(size_t)N_NODES * FEATS];   // inv-degree folded in
__device__ float g_ms[N_NODES];                     // (sum m)/deg

// ---------------- K0: zero the per-node accumulators ----------------
__global__ void k_init() {
    int i = blockIdx.x * blockDim.x + threadIdx.x;
    if (i < N_NODES) {
        g_wsum[i] = 0.0f;
        g_deg[i] = 0;
        g_cursor[i] = 0;
    }
}

// ---------------- K1: per-dst edge-weight sum + degree ----------------
__global__ void k_stats(const float* __restrict__ efeat,
                        const int* __restrict__ dst) {
    int e = blockIdx.x * blockDim.x + threadIdx.x;
    if (e < N_EDGES) {
        int d = dst[e];
        atomicAdd(&g_wsum[d], efeat[e]);
        atomicAdd(&g_deg[d], 1);
    }
}

// ---------------- K2: single-block exclusive scan of degrees ----------------
__global__ void k_scan() {
    __shared__ int sh[1024];
    const int CH = (N_NODES + 1023) / 1024;   // 49
    int t = threadIdx.x;
    int lo = t * CH;
    int hi = lo + CH; if (hi > N_NODES) hi = N_NODES;
    int s = 0;
    for (int i = lo; i < hi && i >= 0; i++) s += g_deg[i];
    sh[t] = s;
    __syncthreads();
    // Hillis-Steele inclusive scan
    for (int off = 1; off < 1024; off <<= 1) {
        int v = (t >= off) ? sh[t - off] : 0;
        __syncthreads();
        sh[t] += v;
        __syncthreads();
    }
    int run = sh[t] - s;   // exclusive prefix
    for (int i = lo; i < hi && i >= 0; i++) {
        g_off[i] = run;
        run += g_deg[i];
    }
}

// ---------------- K3: fill CSR with (src, coef) per edge ----------------
__global__ void k_fill(const float* __restrict__ efeat,
                       const int* __restrict__ src,
                       const int* __restrict__ dst) {
    int e = blockIdx.x * blockDim.x + threadIdx.x;
    if (e < N_EDGES) {
        int d = dst[e];
        float w = efeat[e];
        float m = __expf(-(w / g_wsum[d]));   // wsum>0 whenever node has edges
        int p = g_off[d] + atomicAdd(&g_cursor[d], 1);
        g_esrc[p]  = src[e];
        g_ecoef[p] = m;
    }
}

// ---------------- K4: warp-per-node gather (no feature atomics) ----------------
__global__ void k_gather(const float* __restrict__ feat) {
    int node = (blockIdx.x * blockDim.x + threadIdx.x) >> 5;
    int lane = threadIdx.x & 31;
    if (node >= N_NODES) return;
    int n   = g_deg[node];
    int off = g_off[node];
    const float4* f4 = (const float4*)feat;
    float4 acc = make_float4(0.f, 0.f, 0.f, 0.f);
    float msum = 0.f;
    #pragma unroll 2
    for (int j = 0; j < n; j++) {
        int   s = g_esrc[off + j];    // broadcast load
        float c = g_ecoef[off + j];   // broadcast load
        msum += c;
        float4 f = f4[(size_t)s * 32 + lane];
        acc.x = fmaf(c, f.x, acc.x);
        acc.y = fmaf(c, f.y, acc.y);
        acc.z = fmaf(c, f.z, acc.z);
        acc.w = fmaf(c, f.w, acc.w);
    }
    float inv = 1.0f / fmaxf((float)n, 1.0f);
    ((float4*)g_aggF)[(size_t)node * 32 + lane] =
        make_float4(acc.x * inv, acc.y * inv, acc.z * inv, acc.w * inv);
    if (lane == 0) g_ms[node] = msum * inv;
}

// ---------------- K5: fused GEMM  out = feat@Ws^T + aggF@Wp^T + bs + ms*bp ----
// M=50000, N=128, K=256 (concat).  BM=128 rows/block, 256 threads, 8x8 microtile.
#define BM 128
#define KC 32
#define KTOT 256
#define SPAD 129   // odd stride: conflict-free STS and LDS

__global__ __launch_bounds__(256) void k_gemm(
        const float* __restrict__ feat,
        const float* __restrict__ W_pool,
        const float* __restrict__ b_pool,
        const float* __restrict__ W_self,
        const float* __restrict__ b_self,
        float* __restrict__ out) {
    __shared__ float sA[KC][SPAD];
    __shared__ float sB[KC][SPAD];

    int tid = threadIdx.x;
    int tr = tid >> 4;     // 0..15 -> rows tr*8..tr*8+7
    int tc = tid & 15;     // 0..15 -> cols tc, tc+16, ..., tc+112
    int blockRow = blockIdx.x * BM;

    float acc[8][8];
    #pragma unroll
    for (int r = 0; r < 8; r++)
        #pragma unroll
        for (int c = 0; c < 8; c++) acc[r][c] = 0.f;

    for (int k0 = 0; k0 < KTOT; k0 += KC) {
        const float* Asrc = (k0 < FEATS) ? feat   : g_aggF;
        const float* Bsrc = (k0 < FEATS) ? W_self : W_pool;
        int kOff = k0 & (FEATS - 1);

        // load tiles: 1024 float4 slots, 4 per thread
        #pragma unroll
        for (int it = 0; it < 4; it++) {
            int idx = tid + it * 256;      // 0..1023
            int row = idx >> 3;            // 0..127
            int kq  = idx & 7;             // float4 within chunk
            int k = kq * 4;
            int rg = blockRow + row;
            int rgc = (rg < N_NODES) ? rg : (N_NODES - 1);
            float4 av = *(const float4*)(Asrc + (size_t)rgc * FEATS + kOff + k);
            sA[k + 0][row] = av.x;
            sA[k + 1][row] = av.y;
            sA[k + 2][row] = av.z;
            sA[k + 3][row] = av.w;
            // B tile: j = row index of W (output col), transpose into [k][j]
            float4 bv = *(const float4*)(Bsrc + (size_t)row * FEATS + kOff + k);
            sB[k + 0][row] = bv.x;
            sB[k + 1][row] = bv.y;
            sB[k + 2][row] = bv.z;
            sB[k + 3][row] = bv.w;
        }
        __syncthreads();

        #pragma unroll
        for (int k = 0; k < KC; k++) {
            float a[8], b[8];
            #pragma unroll
            for (int r = 0; r < 8; r++) a[r] = sA[k][tr * 8 + r];
            #pragma unroll
            for (int c = 0; c < 8; c++) b[c] = sB[k][tc + 16 * c];
            #pragma unroll
            for (int r = 0; r < 8; r++)
                #pragma unroll
                for (int c = 0; c < 8; c++)
                    acc[r][c] = fmaf(a[r], b[c], acc[r][c]);
        }
        __syncthreads();
    }

    // epilogue
    float bsv[8], bpv[8];
    #pragma unroll
    for (int c = 0; c < 8; c++) {
        int j = tc + 16 * c;
        bsv[c] = b_self[j];
        bpv[c] = b_pool[j];
    }
    #pragma unroll
    for (int r = 0; r < 8; r++) {
        int rg = blockRow + tr * 8 + r;
        if (rg < N_NODES) {
            float msv = g_ms[rg];
            #pragma unroll
            for (int c = 0; c < 8; c++) {
                int j = tc + 16 * c;
                out[(size_t)rg * FEATS + j] = acc[r][c] + bsv[c] + msv * bpv[c];
            }
        }
    }
}

// ---------------- launch ----------------
extern "C" void kernel_launch(void* const* d_in, const int* in_sizes, int n_in,
                              void* d_out, int out_size) {
    const float* feat   = (const float*)d_in[0];
    const float* efeat  = (const float*)d_in[1];
    const int*   src    = (const int*)d_in[2];
    const int*   dst    = (const int*)d_in[3];
    const float* W_pool = (const float*)d_in[4];
    const float* b_pool = (const float*)d_in[5];
    const float* W_self = (const float*)d_in[6];
    const float* b_self = (const float*)d_in[7];
    float* out = (float*)d_out;

    k_init<<<(N_NODES + 255) / 256, 256>>>();
    k_stats<<<(N_EDGES + 255) / 256, 256>>>(efeat, dst);
    k_scan<<<1, 1024>>>();
    k_fill<<<(N_EDGES + 255) / 256, 256>>>(efeat, src, dst);
    k_gather<<<(N_NODES * 32 + 255) / 256, 256>>>(feat);
    k_gemm<<<(N_NODES + BM - 1) / BM, 256>>>(feat, W_pool, b_pool, W_self, b_self, out);
}

// round 2
// speedup vs baseline: 1.1259x; 1.1259x over previous
#include <cuda_runtime.h>
#include <math.h>

#define N_NODES 50000
#define N_EDGES 800000
#define FEATS   128

// ---------------- scratch (static __device__, no allocation) ----------------
__device__ float g_wsum[N_NODES];
__device__ int   g_deg[N_NODES];
__device__ int   g_cursor[N_NODES];
__device__ int   g_off[N_NODES];
__device__ unsigned long long g_epack[N_EDGES];     // low32 = src, high32 = coef bits
__device__ float g_aggF[(size_t)N_NODES * FEATS];   // inv-degree folded in
__device__ float g_ms[N_NODES];                     // (sum m)/deg

// ---------------- K0: zero the per-node accumulators ----------------
__global__ void k_init() {
    int i = blockIdx.x * blockDim.x + threadIdx.x;
    if (i < N_NODES) {
        g_wsum[i] = 0.0f;
        g_deg[i] = 0;
        g_cursor[i] = 0;
    }
}

// ---------------- K1: per-dst edge-weight sum + degree ----------------
__global__ void k_stats(const float* __restrict__ efeat,
                        const int* __restrict__ dst) {
    int e = blockIdx.x * blockDim.x + threadIdx.x;
    if (e < N_EDGES) {
        int d = dst[e];
        atomicAdd(&g_wsum[d], efeat[e]);
        atomicAdd(&g_deg[d], 1);
    }
}

// ---------------- K2: single-block exclusive scan of degrees ----------------
__global__ void k_scan() {
    __shared__ int sh[1024];
    const int CH = (N_NODES + 1023) / 1024;   // 49
    int t = threadIdx.x;
    int lo = t * CH;
    int hi = lo + CH; if (hi > N_NODES) hi = N_NODES;
    int s = 0;
    for (int i = lo; i < hi && i >= 0; i++) s += g_deg[i];
    sh[t] = s;
    __syncthreads();
    for (int off = 1; off < 1024; off <<= 1) {
        int v = (t >= off) ? sh[t - off] : 0;
        __syncthreads();
        sh[t] += v;
        __syncthreads();
    }
    int run = sh[t] - s;   // exclusive prefix
    for (int i = lo; i < hi && i >= 0; i++) {
        g_off[i] = run;
        run += g_deg[i];
    }
}

// ---------------- K3: fill CSR, packed (src, coef) as one 64-bit store ----
__global__ void k_fill(const float* __restrict__ efeat,
                       const int* __restrict__ src,
                       const int* __restrict__ dst) {
    int e = blockIdx.x * blockDim.x + threadIdx.x;
    if (e < N_EDGES) {
        int d = dst[e];
        float w = efeat[e];
        float m = __expf(-(w / g_wsum[d]));   // wsum>0 whenever node has edges
        int p = g_off[d] + atomicAdd(&g_cursor[d], 1);
        unsigned long long v = (unsigned int)src[e]
                             | ((unsigned long long)__float_as_uint(m) << 32);
        g_epack[p] = v;
    }
}

// ---------------- K4: warp-per-node gather (no feature atomics) ----------------
__global__ void k_gather(const float* __restrict__ feat) {
    int node = (blockIdx.x * blockDim.x + threadIdx.x) >> 5;
    int lane = threadIdx.x & 31;
    if (node >= N_NODES) return;
    int n   = g_deg[node];
    int off = g_off[node];
    const float4* f4 = (const float4*)feat;
    float4 acc = make_float4(0.f, 0.f, 0.f, 0.f);
    float msum = 0.f;
    #pragma unroll 4
    for (int j = 0; j < n; j++) {
        unsigned long long v = g_epack[off + j];   // broadcast 64-bit load
        int   s = (int)(unsigned int)v;
        float c = __uint_as_float((unsigned int)(v >> 32));
        msum += c;
        float4 f = f4[(size_t)s * 32 + lane];
        acc.x = fmaf(c, f.x, acc.x);
        acc.y = fmaf(c, f.y, acc.y);
        acc.z = fmaf(c, f.z, acc.z);
        acc.w = fmaf(c, f.w, acc.w);
    }
    float inv = 1.0f / fmaxf((float)n, 1.0f);
    ((float4*)g_aggF)[(size_t)node * 32 + lane] =
        make_float4(acc.x * inv, acc.y * inv, acc.z * inv, acc.w * inv);
    if (lane == 0) g_ms[node] = msum * inv;
}

// ---------------- K5: fused GEMM  out = feat@Ws^T + aggF@Wp^T + bs + ms*bp ----
// M=50000, N=128, K=256 (concat). BM=128 rows/block, 256 threads.
// Microtile: 8 rows x 4 column-PAIRS per thread, computed with fma.rn.f32x2
// (FFMA2: 2 FMAs per issue -> 2x the FFMA-3reg rate on sm_103a).
#define BM 128
#define KC 32
#define KTOT 256
#define SPAD 130   // even stride: 8-byte aligned rows for LDS.64 B-pair reads

__device__ __forceinline__ unsigned long long f32x2_dup(float a) {
    unsigned long long r;
    asm("mov.b64 %0, {%1, %1};" : "=l"(r) : "f"(a));
    return r;
}
__device__ __forceinline__ void f32x2_fma(unsigned long long& d,
                                          unsigned long long a,
                                          unsigned long long b) {
    asm("fma.rn.f32x2 %0, %1, %2, %0;" : "+l"(d) : "l"(a), "l"(b));
}
__device__ __forceinline__ float2 f32x2_unpack(unsigned long long v) {
    float2 r;
    asm("mov.b64 {%0, %1}, %2;" : "=f"(r.x), "=f"(r.y) : "l"(v));
    return r;
}

__global__ __launch_bounds__(256) void k_gemm(
        const float* __restrict__ feat,
        const float* __restrict__ W_pool,
        const float* __restrict__ b_pool,
        const float* __restrict__ W_self,
        const float* __restrict__ b_self,
        float* __restrict__ out) {
    __shared__ float sA[KC][SPAD];
    __shared__ float sB[KC][SPAD];

    int tid = threadIdx.x;
    int tr = tid >> 4;     // 0..15 -> rows tr*8 .. tr*8+7
    int tc = tid & 15;     // 0..15 -> col pairs (2tc+32j, 2tc+32j+1), j=0..3
    int blockRow = blockIdx.x * BM;

    unsigned long long acc[8][4];
    #pragma unroll
    for (int r = 0; r < 8; r++)
        #pragma unroll
        for (int j = 0; j < 4; j++) acc[r][j] = 0ull;

    for (int k0 = 0; k0 < KTOT; k0 += KC) {
        const float* Asrc = (k0 < FEATS) ? feat   : g_aggF;
        const float* Bsrc = (k0 < FEATS) ? W_self : W_pool;
        int kOff = k0 & (FEATS - 1);

        // load tiles: 1024 float4 slots, 4 per thread
        #pragma unroll
        for (int it = 0; it < 4; it++) {
            int idx = tid + it * 256;      // 0..1023
            int row = idx >> 3;            // 0..127
            int kq  = idx & 7;
            int k = kq * 4;
            int rg = blockRow + row;
            int rgc = (rg < N_NODES) ? rg : (N_NODES - 1);
            float4 av = *(const float4*)(Asrc + (size_t)rgc * FEATS + kOff + k);
            sA[k + 0][row] = av.x;
            sA[k + 1][row] = av.y;
            sA[k + 2][row] = av.z;
            sA[k + 3][row] = av.w;
            float4 bv = *(const float4*)(Bsrc + (size_t)row * FEATS + kOff + k);
            sB[k + 0][row] = bv.x;
            sB[k + 1][row] = bv.y;
            sB[k + 2][row] = bv.z;
            sB[k + 3][row] = bv.w;
        }
        __syncthreads();

        #pragma unroll
        for (int k = 0; k < KC; k++) {
            // B pairs: 64-bit conflict-free loads (row base 8B-aligned, SPAD even)
            const unsigned long long* brow = (const unsigned long long*)&sB[k][0];
            unsigned long long bp[4];
            #pragma unroll
            for (int j = 0; j < 4; j++) bp[j] = brow[tc + 16 * j];
            float a[8];
            #pragma unroll
            for (int r = 0; r < 8; r++) a[r] = sA[k][tr * 8 + r];
            #pragma unroll
            for (int r = 0; r < 8; r++) {
                unsigned long long ap = f32x2_dup(a[r]);
                #pragma unroll
                for (int j = 0; j < 4; j++) f32x2_fma(acc[r][j], ap, bp[j]);
            }
        }
        __syncthreads();
    }

    // epilogue: out = acc + b_self + ms * b_pool   (stores as float2)
    float2 bsv[4], bpv[4];
    #pragma unroll
    for (int j = 0; j < 4; j++) {
        int c0 = 2 * tc + 32 * j;
        bsv[j] = *(const float2*)(b_self + c0);
        bpv[j] = *(const float2*)(b_pool + c0);
    }
    #pragma unroll
    for (int r = 0; r < 8; r++) {
        int rg = blockRow + tr * 8 + r;
        if (rg < N_NODES) {
            float msv = g_ms[rg];
            #pragma unroll
            for (int j = 0; j < 4; j++) {
                int c0 = 2 * tc + 32 * j;
                float2 v = f32x2_unpack(acc[r][j]);
                v.x = v.x + bsv[j].x + msv * bpv[j].x;
                v.y = v.y + bsv[j].y + msv * bpv[j].y;
                *(float2*)(out + (size_t)rg * FEATS + c0) = v;
            }
        }
    }
}

// ---------------- launch ----------------
extern "C" void kernel_launch(void* const* d_in, const int* in_sizes, int n_in,
                              void* d_out, int out_size) {
    const float* feat   = (const float*)d_in[0];
    const float* efeat  = (const float*)d_in[1];
    const int*   src    = (const int*)d_in[2];
    const int*   dst    = (const int*)d_in[3];
    const float* W_pool = (const float*)d_in[4];
    const float* b_pool = (const float*)d_in[5];
    const float* W_self = (const float*)d_in[6];
    const float* b_self = (const float*)d_in[7];
    float* out = (float*)d_out;

    k_init<<<(N_NODES + 255) / 256, 256>>>();
    k_stats<<<(N_EDGES + 255) / 256, 256>>>(efeat, dst);
    k_scan<<<1, 1024>>>();
    k_fill<<<(N_EDGES + 255) / 256, 256>>>(efeat, src, dst);
    k_gather<<<(N_NODES * 32 + 255) / 256, 256>>>(feat);
    k_gemm<<<(N_NODES + BM - 1) / BM, 256>>>(feat, W_pool, b_pool, W_self, b_self, out);
}

// round 4
// speedup vs baseline: 1.2782x; 1.1353x over previous
#include <cuda_runtime.h>
#include <cuda_bf16.h>
#include <cstdint>
#include <math.h>

#define N_NODES 50000
#define N_EDGES 800000
#define FEATS   128

// ---------------- scratch (static __device__, no allocation) ----------------
__device__ float g_wsum[N_NODES];
__device__ int   g_deg[N_NODES];
__device__ int   g_cursor[N_NODES];
__device__ int   g_off[N_NODES];
__device__ unsigned long long g_epack[N_EDGES];     // low32 = src, high32 = coef bits
__device__ float g_aggF[(size_t)N_NODES * FEATS];   // inv-degree folded in
__device__ float g_ms[N_NODES];                     // (sum m)/deg

// ---------------- K0 ----------------
__global__ void k_init() {
    int i = blockIdx.x * blockDim.x + threadIdx.x;
    if (i < N_NODES) { g_wsum[i] = 0.0f; g_deg[i] = 0; g_cursor[i] = 0; }
}

// ---------------- K1: per-dst weight sum + degree ----------------
__global__ void k_stats(const float* __restrict__ efeat, const int* __restrict__ dst) {
    int e = blockIdx.x * blockDim.x + threadIdx.x;
    if (e < N_EDGES) {
        int d = dst[e];
        atomicAdd(&g_wsum[d], efeat[e]);
        atomicAdd(&g_deg[d], 1);
    }
}

// ---------------- K2: single-block exclusive scan ----------------
__global__ void k_scan() {
    __shared__ int sh[1024];
    const int CH = (N_NODES + 1023) / 1024;
    int t = threadIdx.x;
    int lo = t * CH;
    int hi = lo + CH; if (hi > N_NODES) hi = N_NODES;
    int s = 0;
    for (int i = lo; i < hi && i >= 0; i++) s += g_deg[i];
    sh[t] = s;
    __syncthreads();
    for (int off = 1; off < 1024; off <<= 1) {
        int v = (t >= off) ? sh[t - off] : 0;
        __syncthreads();
        sh[t] += v;
        __syncthreads();
    }
    int run = sh[t] - s;
    for (int i = lo; i < hi && i >= 0; i++) { g_off[i] = run; run += g_deg[i]; }
}

// ---------------- K3: fill CSR, packed (src, coef) ----------------
__global__ void k_fill(const float* __restrict__ efeat, const int* __restrict__ src,
                       const int* __restrict__ dst) {
    int e = blockIdx.x * blockDim.x + threadIdx.x;
    if (e < N_EDGES) {
        int d = dst[e];
        float m = __expf(-(efeat[e] / g_wsum[d]));
        int p = g_off[d] + atomicAdd(&g_cursor[d], 1);
        g_epack[p] = (unsigned int)src[e]
                   | ((unsigned long long)__float_as_uint(m) << 32);
    }
}

// ---------------- K4: warp-per-node gather ----------------
__global__ void k_gather(const float* __restrict__ feat) {
    int node = (blockIdx.x * blockDim.x + threadIdx.x) >> 5;
    int lane = threadIdx.x & 31;
    if (node >= N_NODES) return;
    int n   = g_deg[node];
    int off = g_off[node];
    const float4* f4 = (const float4*)feat;
    float4 acc = make_float4(0.f, 0.f, 0.f, 0.f);
    float msum = 0.f;
    #pragma unroll 4
    for (int j = 0; j < n; j++) {
        unsigned long long v = g_epack[off + j];
        int   s = (int)(unsigned int)v;
        float c = __uint_as_float((unsigned int)(v >> 32));
        msum += c;
        float4 f = f4[(size_t)s * 32 + lane];
        acc.x = fmaf(c, f.x, acc.x);
        acc.y = fmaf(c, f.y, acc.y);
        acc.z = fmaf(c, f.z, acc.z);
        acc.w = fmaf(c, f.w, acc.w);
    }
    float inv = 1.0f / fmaxf((float)n, 1.0f);
    ((float4*)g_aggF)[(size_t)node * 32 + lane] =
        make_float4(acc.x * inv, acc.y * inv, acc.z * inv, acc.w * inv);
    if (lane == 0) g_ms[node] = msum * inv;
}

// ============================================================================
// K5: split-bf16 GEMM on mma.sync (HMMA).  out = [feat|aggF]@[Ws;Wp]^T + bias
// D(f32) = Ah*Bh + Ah*Bl + Al*Bh ; per-CTA 128x128, K=256 in 8 chunks of 32.
// 8 warps (4x2), warp tile 32x64 via m16n8k16.
// ============================================================================

#define MMA_BF16(d, A0, A1, A2, A3, B0, B1)                                  \
    asm volatile(                                                            \
        "mma.sync.aligned.m16n8k16.row.col.f32.bf16.bf16.f32 "               \
        "{%0,%1,%2,%3}, {%4,%5,%6,%7}, {%8,%9}, {%0,%1,%2,%3};"              \
        : "+f"(d[0]), "+f"(d[1]), "+f"(d[2]), "+f"(d[3])                     \
        : "r"(A0), "r"(A1), "r"(A2), "r"(A3), "r"(B0), "r"(B1))

__device__ __forceinline__ uint32_t pack_bf16(float a, float b) {
    __nv_bfloat16 x = __float2bfloat16(a);
    __nv_bfloat16 y = __float2bfloat16(b);
    return (uint32_t)__bfloat16_as_ushort(x) | ((uint32_t)__bfloat16_as_ushort(y) << 16);
}

// smem: 4 tiles of 128 rows x 36 bf16 (32 data + 4 pad) = 9216 B each
#define T_AH 0
#define T_AL 9216
#define T_BH 18432
#define T_BL 27648
#define ROWB 72      // bytes per row
#define ROWW 18      // 32-bit words per row

__global__ __launch_bounds__(256, 2) void k_gemm(
        const float* __restrict__ feat,
        const float* __restrict__ W_pool,
        const float* __restrict__ b_pool,
        const float* __restrict__ W_self,
        const float* __restrict__ b_self,
        float* __restrict__ out) {
    __shared__ __align__(16) char sm[36864];

    int tid  = threadIdx.x;
    int wid  = tid >> 5;
    int lane = tid & 31;
    int wr = wid >> 1;          // 0..3  -> 32 M-rows each
    int wc = wid & 1;           // 0..1  -> 64 N-cols each
    int lr = lane >> 2;         // 0..7
    int lc = lane & 3;          // 0..3
    int blockRow = blockIdx.x * 128;

    float acc[2][8][4];
    #pragma unroll
    for (int mt = 0; mt < 2; mt++)
        #pragma unroll
        for (int nt = 0; nt < 8; nt++)
            #pragma unroll
            for (int i = 0; i < 4; i++) acc[mt][nt][i] = 0.f;

    for (int c = 0; c < 8; c++) {
        const float* Asrc = (c < 4) ? feat   : g_aggF;
        const float* Bsrc = (c < 4) ? W_self : W_pool;
        int kOff = (c & 3) * 32;

        __syncthreads();   // previous chunk's compute done before overwrite
        #pragma unroll
        for (int it = 0; it < 4; it++) {
            int idx = tid + it * 256;     // 0..1023 float4 slots
            int row = idx >> 3;           // 0..127
            int q   = idx & 7;
            int k0  = q * 4;
            // ---- A ----
            int rg  = blockRow + row;
            int rgc = (rg < N_NODES) ? rg : (N_NODES - 1);
            float4 v = *(const float4*)(Asrc + (size_t)rgc * FEATS + kOff + k0);
            float hx = __bfloat162float(__float2bfloat16(v.x));
            float hy = __bfloat162float(__float2bfloat16(v.y));
            float hz = __bfloat162float(__float2bfloat16(v.z));
            float hw = __bfloat162float(__float2bfloat16(v.w));
            uint2 hp, lp;
            hp.x = pack_bf16(hx, hy);           hp.y = pack_bf16(hz, hw);
            lp.x = pack_bf16(v.x - hx, v.y - hy); lp.y = pack_bf16(v.z - hz, v.w - hw);
            *(uint2*)(sm + T_AH + row * ROWB + q * 8) = hp;
            *(uint2*)(sm + T_AL + row * ROWB + q * 8) = lp;
            // ---- B ----
            float4 w = *(const float4*)(Bsrc + (size_t)row * FEATS + kOff + k0);
            float gx = __bfloat162float(__float2bfloat16(w.x));
            float gy = __bfloat162float(__float2bfloat16(w.y));
            float gz = __bfloat162float(__float2bfloat16(w.z));
            float gw = __bfloat162float(__float2bfloat16(w.w));
            hp.x = pack_bf16(gx, gy);           hp.y = pack_bf16(gz, gw);
            lp.x = pack_bf16(w.x - gx, w.y - gy); lp.y = pack_bf16(w.z - gz, w.w - gw);
            *(uint2*)(sm + T_BH + row * ROWB + q * 8) = hp;
            *(uint2*)(sm + T_BL + row * ROWB + q * 8) = lp;
        }
        __syncthreads();

        const uint32_t* pAH = (const uint32_t*)(sm + T_AH);
        const uint32_t* pAL = (const uint32_t*)(sm + T_AL);
        const uint32_t* pBH = (const uint32_t*)(sm + T_BH);
        const uint32_t* pBL = (const uint32_t*)(sm + T_BL);

        #pragma unroll
        for (int ks = 0; ks < 2; ks++) {
            int kb2 = ks * 8;   // 16 bf16 = 8 words
            uint32_t ah[2][4], al[2][4];
            #pragma unroll
            for (int mt = 0; mt < 2; mt++) {
                int r0 = wr * 32 + mt * 16 + lr;
                int i00 = r0 * ROWW + kb2 + lc;
                ah[mt][0] = pAH[i00];
                ah[mt][1] = pAH[i00 + 8 * ROWW];
                ah[mt][2] = pAH[i00 + 4];
                ah[mt][3] = pAH[i00 + 8 * ROWW + 4];
                al[mt][0] = pAL[i00];
                al[mt][1] = pAL[i00 + 8 * ROWW];
                al[mt][2] = pAL[i00 + 4];
                al[mt][3] = pAL[i00 + 8 * ROWW + 4];
            }
            #pragma unroll
            for (int nt = 0; nt < 8; nt++) {
                int n0 = wc * 64 + nt * 8 + lr;
                int j0 = n0 * ROWW + kb2 + lc;
                uint32_t bh0 = pBH[j0], bh1 = pBH[j0 + 4];
                uint32_t bl0 = pBL[j0], bl1 = pBL[j0 + 4];
                #pragma unroll
                for (int mt = 0; mt < 2; mt++) {
                    MMA_BF16(acc[mt][nt], ah[mt][0], ah[mt][1], ah[mt][2], ah[mt][3], bh0, bh1);
                    MMA_BF16(acc[mt][nt], ah[mt][0], ah[mt][1], ah[mt][2], ah[mt][3], bl0, bl1);
                    MMA_BF16(acc[mt][nt], al[mt][0], al[mt][1], al[mt][2], al[mt][3], bh0, bh1);
                }
            }
        }
    }

    // ---- epilogue: + b_self + ms * b_pool ----
    #pragma unroll
    for (int mt = 0; mt < 2; mt++) {
        int r0 = blockRow + wr * 32 + mt * 16 + lr;
        int r1 = r0 + 8;
        float ms0 = (r0 < N_NODES) ? g_ms[r0] : 0.f;
        float ms1 = (r1 < N_NODES) ? g_ms[r1] : 0.f;
        #pragma unroll
        for (int nt = 0; nt < 8; nt++) {
            int C = wc * 64 + nt * 8 + lc * 2;
            float2 bs = *(const float2*)(b_self + C);
            float2 bp = *(const float2*)(b_pool + C);
            if (r0 < N_NODES) {
                float2 o;
                o.x = acc[mt][nt][0] + bs.x + ms0 * bp.x;
                o.y = acc[mt][nt][1] + bs.y + ms0 * bp.y;
                *(float2*)(out + (size_t)r0 * FEATS + C) = o;
            }
            if (r1 < N_NODES) {
                float2 o;
                o.x = acc[mt][nt][2] + bs.x + ms1 * bp.x;
                o.y = acc[mt][nt][3] + bs.y + ms1 * bp.y;
                *(float2*)(out + (size_t)r1 * FEATS + C) = o;
            }
        }
    }
}

// ---------------- launch ----------------
extern "C" void kernel_launch(void* const* d_in, const int* in_sizes, int n_in,
                              void* d_out, int out_size) {
    const float* feat   = (const float*)d_in[0];
    const float* efeat  = (const float*)d_in[1];
    const int*   src    = (const int*)d_in[2];
    const int*   dst    = (const int*)d_in[3];
    const float* W_pool = (const float*)d_in[4];
    const float* b_pool = (const float*)d_in[5];
    const float* W_self = (const float*)d_in[6];
    const float* b_self = (const float*)d_in[7];
    float* out = (float*)d_out;

    k_init<<<(N_NODES + 255) / 256, 256>>>();
    k_stats<<<(N_EDGES + 255) / 256, 256>>>(efeat, dst);
    k_scan<<<1, 1024>>>();
    k_fill<<<(N_EDGES + 255) / 256, 256>>>(efeat, src, dst);
    k_gather<<<(N_NODES * 32 + 255) / 256, 256>>>(feat);
    k_gemm<<<(N_NODES + 127) / 128, 256>>>(feat, W_pool, b_pool, W_self, b_self, out);
}